// round 1
// baseline (speedup 1.0000x reference)
#include <cuda_runtime.h>
#include <mma.h>

using namespace nvcuda;

#define NROWS 200000
#define CCH   128
#define TM    64
#define NBLK  (NROWS / TM)     // 3125 exactly
#define BN_EPS 1e-5f

// Scratch (allocation-free: __device__ globals)
__device__ float g_out  [(size_t)3 * NROWS * CCH];      // 307.2 MB: pre-BN GEMM outputs per axis
__device__ float g_part [(size_t)3 * NBLK * 2 * CCH];   // per-block column {sum, sumsq}
__device__ float g_stats[3 * 2 * CCH];                  // per-axis {mu, rstd}

// ---------------------------------------------------------------------------
// K1: for each axis a, out[N,128] = gather_prev @ W[a,0] + x @ W[a,1] + gather_next @ W[a,2]
// One block = 64 rows x 128 cols, K=384 in 12 chunks of 32, wmma tf32 16x16x8.
// Also emits per-block column sum / sumsq partials for BatchNorm.
// ---------------------------------------------------------------------------
__global__ __launch_bounds__(256) void k1_gemm(const float* __restrict__ feat,
                                               const int*   __restrict__ nb,
                                               const float* __restrict__ W)
{
    const int a    = blockIdx.y;
    const int row0 = blockIdx.x * TM;
    const int t    = threadIdx.x;
    const int warp = t >> 5;
    const int wm   = warp >> 1;   // 0..3 -> 16-row strip
    const int wn   = warp & 1;    // 0..1 -> 64-col half

    __shared__ float As[TM][40];   // 64 x 32 (+pad)
    __shared__ float Bs[32][136];  // 32 x 128 (+pad)

    wmma::fragment<wmma::accumulator, 16, 16, 8, float> acc[4];
#pragma unroll
    for (int f = 0; f < 4; f++) wmma::fill_fragment(acc[f], 0.0f);

    for (int kt = 0; kt < 12; kt++) {
        const int seg = kt >> 2;          // 0: prev, 1: self, 2: next
        const int kk  = (kt & 3) * 32;    // column offset within the 128-wide segment

        // ---- load A tile (gathered): 64 rows x 32 cols = 512 float4
#pragma unroll
        for (int i = 0; i < 2; i++) {
            int vid = t + i * 256;        // 0..511
            int r   = vid >> 3;
            int c4  = vid & 7;
            int gr  = row0 + r;
            int idx;
            if (seg == 1) idx = gr;
            else          idx = nb[((size_t)(a * 2 + (seg >> 1))) * NROWS + gr];
            float4 v = make_float4(0.f, 0.f, 0.f, 0.f);
            if (idx < NROWS)
                v = *(const float4*)(feat + (size_t)idx * CCH + kk + c4 * 4);
            *(float4*)(&As[r][c4 * 4]) = v;
        }
        // ---- load B tile: W[a][seg][kk + 0..31][0..127] = 1024 float4
#pragma unroll
        for (int i = 0; i < 4; i++) {
            int vid = t + i * 256;        // 0..1023
            int r   = vid >> 5;
            int n4  = vid & 31;
            float4 v = *(const float4*)(W + (((size_t)(a * 3 + seg) * CCH) + kk + r) * CCH + n4 * 4);
            *(float4*)(&Bs[r][n4 * 4]) = v;
        }
        __syncthreads();

#pragma unroll
        for (int ks = 0; ks < 4; ks++) {
            wmma::fragment<wmma::matrix_a, 16, 16, 8, wmma::precision::tf32, wmma::row_major> af;
            wmma::load_matrix_sync(af, &As[wm * 16][ks * 8], 40);
#pragma unroll
            for (int i = 0; i < af.num_elements; i++) af.x[i] = wmma::__float_to_tf32(af.x[i]);
#pragma unroll
            for (int f = 0; f < 4; f++) {
                wmma::fragment<wmma::matrix_b, 16, 16, 8, wmma::precision::tf32, wmma::row_major> bf;
                wmma::load_matrix_sync(bf, &Bs[ks * 8][wn * 64 + f * 16], 136);
#pragma unroll
                for (int i = 0; i < bf.num_elements; i++) bf.x[i] = wmma::__float_to_tf32(bf.x[i]);
                wmma::mma_sync(acc[f], af, bf, acc[f]);
            }
        }
        __syncthreads();
    }

    // ---- store tile to scratch
#pragma unroll
    for (int f = 0; f < 4; f++) {
        float* p = g_out + ((size_t)a * NROWS + row0 + wm * 16) * CCH + wn * 64 + f * 16;
        wmma::store_matrix_sync(p, acc[f], CCH, wmma::mem_row_major);
    }
    __syncthreads();  // makes the global stores visible block-wide

    // ---- per-block column partials (deterministic, no atomics)
    if (t < CCH) {
        float s = 0.f, s2 = 0.f;
        const float* p = g_out + ((size_t)a * NROWS + row0) * CCH + t;
#pragma unroll 8
        for (int r = 0; r < TM; r++) {
            float v = p[(size_t)r * CCH];
            s += v; s2 += v * v;
        }
        g_part[(((size_t)a * NBLK + blockIdx.x) * 2 + 0) * CCH + t] = s;
        g_part[(((size_t)a * NBLK + blockIdx.x) * 2 + 1) * CCH + t] = s2;
    }
}

// ---------------------------------------------------------------------------
// K2: reduce partials -> mu, rstd per (axis, channel). 3 blocks x 256 threads.
// Fixed order, double accumulation -> deterministic and accurate.
// ---------------------------------------------------------------------------
__global__ __launch_bounds__(256) void k2_stats()
{
    const int a = blockIdx.x;
    const int t = threadIdx.x;          // 0..255 -> [stat][channel]
    double acc = 0.0;
    const float* p = g_part + (size_t)a * NBLK * 2 * CCH + t;
    for (int b = 0; b < NBLK; b++) acc += (double)p[(size_t)b * 2 * CCH];

    __shared__ double sd[256];
    sd[t] = acc;
    __syncthreads();
    if (t < CCH) {
        double mu  = sd[t] / (double)NROWS;
        double var = sd[t + CCH] / (double)NROWS - mu * mu;
        g_stats[(a * 2 + 0) * CCH + t] = (float)mu;
        g_stats[(a * 2 + 1) * CCH + t] = rsqrtf((float)var + BN_EPS);
    }
}

// ---------------------------------------------------------------------------
// K3: acc = sum_a sigmoid((out_a - mu)*rstd*gamma + beta); result = acc * features
// float4 vectorized elementwise pass.
// ---------------------------------------------------------------------------
__global__ __launch_bounds__(256) void k3_final(const float* __restrict__ feat,
                                                const float* __restrict__ gamma,
                                                const float* __restrict__ beta,
                                                float* __restrict__ out)
{
    const size_t i  = (size_t)blockIdx.x * 256 + threadIdx.x;  // float4 index
    const size_t nv = (size_t)NROWS * CCH / 4;
    if (i >= nv) return;
    const int cbase = (int)(i & (CCH / 4 - 1)) * 4;

    float4 f4 = ((const float4*)feat)[i];
    float f[4]   = { f4.x, f4.y, f4.z, f4.w };
    float acc[4] = { 0.f, 0.f, 0.f, 0.f };

#pragma unroll
    for (int a = 0; a < 3; a++) {
        float4 o4 = *(const float4*)(g_out + (size_t)a * NROWS * CCH + i * 4);
        float o[4] = { o4.x, o4.y, o4.z, o4.w };
#pragma unroll
        for (int j = 0; j < 4; j++) {
            int c = cbase + j;
            float mu = g_stats[(a * 2 + 0) * CCH + c];
            float rs = g_stats[(a * 2 + 1) * CCH + c];
            float gm = gamma[a * CCH + c];
            float bt = beta [a * CCH + c];
            float x  = (o[j] - mu) * rs * gm + bt;
            acc[j] += 1.0f / (1.0f + __expf(-x));
        }
    }
    float4 r = make_float4(acc[0] * f[0], acc[1] * f[1], acc[2] * f[2], acc[3] * f[3]);
    ((float4*)out)[i] = r;
}

// ---------------------------------------------------------------------------
extern "C" void kernel_launch(void* const* d_in, const int* in_sizes, int n_in,
                              void* d_out, int out_size)
{
    const float* feat  = (const float*)d_in[0];  // [N,128]
    const int*   nb    = (const int*)  d_in[1];  // [3,2,N]
    const float* W     = (const float*)d_in[2];  // [3,3,128,128]
    const float* gamma = (const float*)d_in[3];  // [3,128]
    const float* beta  = (const float*)d_in[4];  // [3,128]

    dim3 g1(NBLK, 3);
    k1_gemm<<<g1, 256>>>(feat, nb, W);
    k2_stats<<<3, 256>>>();
    k3_final<<<(unsigned)((size_t)NROWS * CCH / 4 / 256), 256>>>(feat, gamma, beta, (float*)d_out);
}

// round 3
// speedup vs baseline: 2.3141x; 2.3141x over previous
#include <cuda_runtime.h>
#include <cuda_fp16.h>
#include <mma.h>

using namespace nvcuda;

#define NROWS 200000
#define CCH   128
#define TM    128
#define TK    32
#define NKT   12                    // K = 384 in chunks of 32
#define NBLK1 ((NROWS + TM - 1) / TM)   // 1563
#define BN_EPS 1e-5f

#define A_LD  40                    // halves, pad for ldmatrix conflicts
#define B_LD  136
#define A_BUF (TM * A_LD)           // 5120 halves / buffer
#define B_BUF (TK * B_LD)           // 4352 halves / buffer
#define OFF_B   20480               // bytes: 2*A_BUF*2
#define OFF_OUT 37888               // bytes: OFF_B + 2*B_BUF*2, 16B aligned
#define SMEM_TOTAL (OFF_OUT + TM * CCH * 4)   // 103424 bytes

// Scratch (allocation-free: __device__ globals)
__device__ float g_out  [(size_t)3 * NROWS * CCH];       // pre-BN GEMM outputs per axis
__device__ float g_part [(size_t)3 * NBLK1 * 2 * CCH];   // per-block column {sum, sumsq}
__device__ float g_stats[3 * 2 * CCH];                   // per-axis {mu, rstd}

// ---------------------------------------------------------------------------
// K1: 128x128 output tile, K=384 (3 gathered segments x 128), fp16 wmma
// m16n16k16 with fp32 accumulators. Register-staged double buffering.
// ---------------------------------------------------------------------------
__global__ void __launch_bounds__(256, 2)
k1_gemm(const float* __restrict__ feat,
        const int*   __restrict__ nb,
        const float* __restrict__ W)
{
    const int a    = blockIdx.y;
    const int row0 = blockIdx.x * TM;
    const int t    = threadIdx.x;
    const int warp = t >> 5;
    const int mg   = warp >> 2;     // 0..1: 64-row half
    const int ng   = warp & 3;      // 0..3: 32-col group

    extern __shared__ char dyn[];
    half*  As   = (half*)dyn;                   // [2][TM][A_LD]
    half*  Bs   = (half*)(dyn + OFF_B);         // [2][TK][B_LD]
    float* OutS = (float*)(dyn + OFF_OUT);      // [TM][CCH]
    float* Pred = (float*)dyn;                  // reuse (As dead): [4][128]

    __shared__ int s_idx[3][TM];

    // precompute gather indices for this block's rows
    if (t < TM) {
        int gr = row0 + t;
        bool ok = gr < NROWS;
        s_idx[1][t] = ok ? gr : NROWS;
        s_idx[0][t] = ok ? nb[(size_t)(a * 2 + 0) * NROWS + gr] : NROWS;
        s_idx[2][t] = ok ? nb[(size_t)(a * 2 + 1) * NROWS + gr] : NROWS;
    }
    __syncthreads();

    wmma::fragment<wmma::accumulator, 16, 16, 16, float> acc[4][2];
#pragma unroll
    for (int i = 0; i < 4; i++)
#pragma unroll
        for (int j = 0; j < 2; j++) wmma::fill_fragment(acc[i][j], 0.0f);

    float4 ra[4], rb[4];

    auto load_tile = [&](int kt) {
        const int seg = kt >> 2;
        const int kk  = (kt & 3) * TK;
        // A: 128 rows x 32 cols = 1024 float4
#pragma unroll
        for (int i = 0; i < 4; i++) {
            int vid = t + i * 256;
            int r   = vid >> 3;
            int c4  = vid & 7;
            int idx = s_idx[seg][r];
            ra[i] = (idx < NROWS)
                  ? *(const float4*)(feat + (size_t)idx * CCH + kk + c4 * 4)
                  : make_float4(0.f, 0.f, 0.f, 0.f);
        }
        // B: 32 rows x 128 cols = 1024 float4
#pragma unroll
        for (int i = 0; i < 4; i++) {
            int vid = t + i * 256;
            int r   = vid >> 5;
            int n4  = vid & 31;
            rb[i] = *(const float4*)(W + (((size_t)(a * 3 + seg) * CCH) + kk + r) * CCH + n4 * 4);
        }
    };

    auto store_tile = [&](int b) {
#pragma unroll
        for (int i = 0; i < 4; i++) {
            int vid = t + i * 256;
            int r   = vid >> 3;
            int c4  = vid & 7;
            half2 h0 = __float22half2_rn(make_float2(ra[i].x, ra[i].y));
            half2 h1 = __float22half2_rn(make_float2(ra[i].z, ra[i].w));
            *(uint2*)(As + b * A_BUF + r * A_LD + c4 * 4) =
                make_uint2(*(unsigned*)&h0, *(unsigned*)&h1);
        }
#pragma unroll
        for (int i = 0; i < 4; i++) {
            int vid = t + i * 256;
            int r   = vid >> 5;
            int n4  = vid & 31;
            half2 h0 = __float22half2_rn(make_float2(rb[i].x, rb[i].y));
            half2 h1 = __float22half2_rn(make_float2(rb[i].z, rb[i].w));
            *(uint2*)(Bs + b * B_BUF + r * B_LD + n4 * 4) =
                make_uint2(*(unsigned*)&h0, *(unsigned*)&h1);
        }
    };

    load_tile(0);
    store_tile(0);
    __syncthreads();

    for (int kt = 0; kt < NKT; kt++) {
        if (kt + 1 < NKT) load_tile(kt + 1);    // global loads in flight during MMA
        const int b = kt & 1;
#pragma unroll
        for (int ks = 0; ks < 2; ks++) {
            wmma::fragment<wmma::matrix_a, 16, 16, 16, half, wmma::row_major> af[4];
#pragma unroll
            for (int i = 0; i < 4; i++)
                wmma::load_matrix_sync(af[i], As + b * A_BUF + (mg * 64 + i * 16) * A_LD + ks * 16, A_LD);
#pragma unroll
            for (int j = 0; j < 2; j++) {
                wmma::fragment<wmma::matrix_b, 16, 16, 16, half, wmma::row_major> bf;
                wmma::load_matrix_sync(bf, Bs + b * B_BUF + (ks * 16) * B_LD + ng * 32 + j * 16, B_LD);
#pragma unroll
                for (int i = 0; i < 4; i++)
                    wmma::mma_sync(acc[i][j], af[i], bf, acc[i][j]);
            }
        }
        if (kt + 1 < NKT) store_tile((kt + 1) & 1);
        __syncthreads();
    }

    // ---- accumulators -> smem out tile
#pragma unroll
    for (int i = 0; i < 4; i++)
#pragma unroll
        for (int j = 0; j < 2; j++)
            wmma::store_matrix_sync(OutS + (mg * 64 + i * 16) * CCH + ng * 32 + j * 16,
                                    acc[i][j], CCH, wmma::mem_row_major);
    __syncthreads();

    const int valid = min(TM, NROWS - row0);

    // ---- vectorized global store of the tile
    float* gptr = g_out + ((size_t)a * NROWS + row0) * CCH;
#pragma unroll
    for (int i = 0; i < 16; i++) {
        int vid = t + i * 256;
        int r   = vid >> 5;
        int c4  = vid & 31;
        if (r < valid)
            ((float4*)(gptr + (size_t)r * CCH))[c4] = ((float4*)(OutS + r * CCH))[c4];
    }

    // ---- BN partials from smem (deterministic, no atomics)
    {
        int col  = t & 127;
        int part = t >> 7;
        int rlo  = part * 64;
        int rhi  = min(rlo + 64, valid);
        float s = 0.f, s2 = 0.f;
        for (int r = rlo; r < rhi; r++) {
            float v = OutS[r * CCH + col];
            s += v; s2 += v * v;
        }
        Pred[part * 128 + col]       = s;
        Pred[256 + part * 128 + col] = s2;
    }
    __syncthreads();
    if (t < CCH) {
        float s  = Pred[t] + Pred[128 + t];
        float s2 = Pred[256 + t] + Pred[384 + t];
        g_part[(((size_t)a * NBLK1 + blockIdx.x) * 2 + 0) * CCH + t] = s;
        g_part[(((size_t)a * NBLK1 + blockIdx.x) * 2 + 1) * CCH + t] = s2;
    }
}

// ---------------------------------------------------------------------------
// K2: reduce partials -> mu, rstd per (axis, channel). Fixed order, double acc.
// ---------------------------------------------------------------------------
__global__ __launch_bounds__(256) void k2_stats()
{
    const int a = blockIdx.x;
    const int t = threadIdx.x;          // [stat][channel]
    double acc = 0.0;
    const float* p = g_part + (size_t)a * NBLK1 * 2 * CCH + t;
    for (int b = 0; b < NBLK1; b++) acc += (double)p[(size_t)b * 2 * CCH];

    __shared__ double sd[256];
    sd[t] = acc;
    __syncthreads();
    if (t < CCH) {
        double mu  = sd[t] / (double)NROWS;
        double var = sd[t + CCH] / (double)NROWS - mu * mu;
        g_stats[(a * 2 + 0) * CCH + t] = (float)mu;
        g_stats[(a * 2 + 1) * CCH + t] = rsqrtf((float)var + BN_EPS);
    }
}

// ---------------------------------------------------------------------------
// K3: acc = sum_a sigmoid((out_a - mu)*rstd*gamma + beta); result = acc * feat
// ---------------------------------------------------------------------------
__global__ __launch_bounds__(256) void k3_final(const float* __restrict__ feat,
                                                const float* __restrict__ gamma,
                                                const float* __restrict__ beta,
                                                float* __restrict__ out)
{
    const size_t i  = (size_t)blockIdx.x * 256 + threadIdx.x;  // float4 index
    const int cbase = (int)(i & (CCH / 4 - 1)) * 4;

    float4 f4 = ((const float4*)feat)[i];
    float f[4]   = { f4.x, f4.y, f4.z, f4.w };
    float acc[4] = { 0.f, 0.f, 0.f, 0.f };

#pragma unroll
    for (int a = 0; a < 3; a++) {
        float4 o4 = *(const float4*)(g_out + (size_t)a * NROWS * CCH + i * 4);
        float o[4] = { o4.x, o4.y, o4.z, o4.w };
#pragma unroll
        for (int j = 0; j < 4; j++) {
            int c = cbase + j;
            float mu = g_stats[(a * 2 + 0) * CCH + c];
            float rs = g_stats[(a * 2 + 1) * CCH + c];
            float x  = (o[j] - mu) * rs * gamma[a * CCH + c] + beta[a * CCH + c];
            acc[j] += 1.0f / (1.0f + __expf(-x));
        }
    }
    ((float4*)out)[i] = make_float4(acc[0] * f[0], acc[1] * f[1],
                                    acc[2] * f[2], acc[3] * f[3]);
}

// ---------------------------------------------------------------------------
extern "C" void kernel_launch(void* const* d_in, const int* in_sizes, int n_in,
                              void* d_out, int out_size)
{
    const float* feat  = (const float*)d_in[0];  // [N,128]
    const int*   nb    = (const int*)  d_in[1];  // [3,2,N]
    const float* W     = (const float*)d_in[2];  // [3,3,128,128]
    const float* gamma = (const float*)d_in[3];  // [3,128]
    const float* beta  = (const float*)d_in[4];  // [3,128]

    cudaFuncSetAttribute(k1_gemm, cudaFuncAttributeMaxDynamicSharedMemorySize, SMEM_TOTAL);

    dim3 g1(NBLK1, 3);
    k1_gemm<<<g1, 256, SMEM_TOTAL>>>(feat, nb, W);
    k2_stats<<<3, 256>>>();
    k3_final<<<(unsigned)((size_t)NROWS * CCH / 4 / 256), 256>>>(feat, gamma, beta, (float*)d_out);
}

// round 7
// speedup vs baseline: 5.1088x; 2.2077x over previous
#include <cuda_runtime.h>
#include <cuda_fp16.h>
#include <mma.h>
#include <cstdint>

using namespace nvcuda;

#define NROWS  200000
#define CCH    128
#define TM     128
#define TK     64                      // K-chunk (fp16 row = 128B)
#define NCHNK  6                       // K = 384 = 6 x 64
#define NBLK1  1563                    // ceil(200000/128)
#define BN_EPS 1e-5f
#define NCH2   25                      // ceil(1563/64)

#define A_LD   72                      // halves (144B rows, 16B aligned)
#define B_LD   136                     // halves (272B rows)
#define A_BYTES (TM * A_LD * 2)        // 18432
#define B_BYTES (TK * B_LD * 2)        // 17408
#define BUF_STRIDE (A_BYTES + B_BYTES) // 35840
#define DYN_SMEM (2 * BUF_STRIDE)      // 71680  (stage fp32 64KB fits inside)

// ---------------- global scratch (allocation-free) ----------------
__device__ __half g_featH[(size_t)NROWS * CCH];          // 51.2 MB fp16 features
__device__ __half g_Wh   [9 * CCH * CCH];                // fp16 W images [a*3+seg][k][n]
__device__ __half g_out  [(size_t)3 * NROWS * CCH];      // 153.6 MB fp16 pre-BN outputs
__device__ float  g_part [(size_t)3 * NBLK1 * 2 * CCH];  // per-tile col {sum,sumsq}
__device__ float  g_p2   [3 * NCH2 * 2 * CCH];
__device__ float  g_scale[3 * CCH];                      // rstd*gamma
__device__ float  g_off  [3 * CCH];                      // beta - mu*rstd*gamma

// ---------------- helpers ----------------
__device__ __forceinline__ uint32_t smem_u32(const void* p) {
    return (uint32_t)__cvta_generic_to_shared(p);
}
__device__ __forceinline__ void cp16(uint32_t dst, const void* src, uint32_t sz) {
    asm volatile("cp.async.cg.shared.global [%0], [%1], 16, %2;"
                 :: "r"(dst), "l"(src), "r"(sz) : "memory");
}
__device__ __forceinline__ void cp_commit() {
    asm volatile("cp.async.commit_group;" ::: "memory");
}
__device__ __forceinline__ void cp_wait0() {
    asm volatile("cp.async.wait_group 0;" ::: "memory");
}

// ---------------------------------------------------------------------------
// K0a: features fp32 -> fp16   (one float4 -> 4 halves per thread)
// ---------------------------------------------------------------------------
__global__ __launch_bounds__(256) void k0_feat(const float* __restrict__ feat)
{
    size_t i = (size_t)blockIdx.x * 256 + threadIdx.x;     // float4 index
    float4 v = ((const float4*)feat)[i];
    __half2 h0 = __floats2half2_rn(v.x, v.y);
    __half2 h1 = __floats2half2_rn(v.z, v.w);
    *(uint2*)(g_featH + i * 4) = make_uint2(*(uint32_t*)&h0, *(uint32_t*)&h1);
}

// ---------------------------------------------------------------------------
// K0b: W fp32 -> fp16 (row-major [img][k][n], verbatim layout)
// ---------------------------------------------------------------------------
__global__ __launch_bounds__(256) void k0_w(const float* __restrict__ W)
{
    size_t i = (size_t)blockIdx.x * 256 + threadIdx.x;     // float4 index, 36864 total
    float4 v = ((const float4*)W)[i];
    __half2 h0 = __floats2half2_rn(v.x, v.y);
    __half2 h1 = __floats2half2_rn(v.z, v.w);
    *(uint2*)(g_Wh + i * 4) = make_uint2(*(uint32_t*)&h0, *(uint32_t*)&h1);
}

// ---------------------------------------------------------------------------
// K1: per (axis, 128-row tile): out = sum_seg gather(A_seg) @ W[a,seg]
// fp16 wmma m16n16k16, K in 6 chunks of 64, cp.async double-buffered.
// ---------------------------------------------------------------------------
__global__ void __launch_bounds__(256, 2)
k1_gemm(const int* __restrict__ nb)
{
    const int a    = blockIdx.y;
    const int row0 = blockIdx.x * TM;
    const int t    = threadIdx.x;
    const int warp = t >> 5;
    const int mg   = warp >> 2;     // 0..1 : 64-row half
    const int ng   = warp & 3;      // 0..3 : 32-col group

    extern __shared__ __align__(1024) char dyn[];
    const uint32_t base32 = smem_u32(dyn);

    __shared__ int   s_idx[3][TM];
    __shared__ float Pred[512];

    if (t < TM) {
        int gr = row0 + t;
        bool ok = gr < NROWS;
        s_idx[1][t] = ok ? gr : NROWS;
        s_idx[0][t] = ok ? nb[(size_t)(a * 2 + 0) * NROWS + gr] : NROWS;
        s_idx[2][t] = ok ? nb[(size_t)(a * 2 + 1) * NROWS + gr] : NROWS;
    }
    __syncthreads();

    auto load_chunk = [&](int i) {
        const int seg = i >> 1;
        const int kk  = (i & 1) * TK;
        const int buf = i & 1;
        const uint32_t abase = base32 + buf * BUF_STRIDE;
        const uint32_t bbase = abase + A_BYTES;
        // A: 128 gathered rows x 64 halves (128B) = 8 x 16B per row
#pragma unroll
        for (int it = 0; it < 4; it++) {
            int vid = t + it * 256;            // 0..1023
            int r   = vid >> 3;
            int c   = vid & 7;
            int idx = s_idx[seg][r];
            uint32_t sz = (idx < NROWS) ? 16u : 0u;
            cp16(abase + r * (A_LD * 2) + c * 16,
                 g_featH + (size_t)idx * CCH + kk + c * 8, sz);
        }
        // B: 64 rows x 128 halves (256B) = 16 x 16B per row
        const __half* wsrc = g_Wh + ((size_t)(a * 3 + seg) * CCH + kk) * CCH;
#pragma unroll
        for (int it = 0; it < 4; it++) {
            int vid = t + it * 256;            // 0..1023
            int r   = vid >> 4;
            int c   = vid & 15;
            cp16(bbase + r * (B_LD * 2) + c * 16, wsrc + r * CCH + c * 8, 16u);
        }
        cp_commit();
    };

    wmma::fragment<wmma::accumulator, 16, 16, 16, float> acc[4][2];
#pragma unroll
    for (int i = 0; i < 4; i++)
#pragma unroll
        for (int j = 0; j < 2; j++) wmma::fill_fragment(acc[i][j], 0.0f);

    load_chunk(0);

    for (int i = 0; i < NCHNK; i++) {
        cp_wait0();
        __syncthreads();
        if (i + 1 < NCHNK) load_chunk(i + 1);

        const int buf = i & 1;
        const half* As = (const half*)(dyn + buf * BUF_STRIDE);
        const half* Bs = (const half*)(dyn + buf * BUF_STRIDE + A_BYTES);
#pragma unroll
        for (int ks = 0; ks < 4; ks++) {
            wmma::fragment<wmma::matrix_a, 16, 16, 16, half, wmma::row_major> af[4];
#pragma unroll
            for (int q = 0; q < 4; q++)
                wmma::load_matrix_sync(af[q], As + (mg * 64 + q * 16) * A_LD + ks * 16, A_LD);
#pragma unroll
            for (int j = 0; j < 2; j++) {
                wmma::fragment<wmma::matrix_b, 16, 16, 16, half, wmma::row_major> bf;
                wmma::load_matrix_sync(bf, Bs + (ks * 16) * B_LD + ng * 32 + j * 16, B_LD);
#pragma unroll
                for (int q = 0; q < 4; q++)
                    wmma::mma_sync(acc[q][j], af[q], bf, acc[q][j]);
            }
        }
        __syncthreads();   // all warps done with buf before it is refilled
    }

    // ---- epilogue: stage fp32 tile in smem (reuses buffers)
    float* stage = (float*)dyn;               // [128][128] fp32 = 64KB
#pragma unroll
    for (int q = 0; q < 4; q++)
#pragma unroll
        for (int j = 0; j < 2; j++)
            wmma::store_matrix_sync(stage + (mg * 64 + q * 16) * CCH + ng * 32 + j * 16,
                                    acc[q][j], CCH, wmma::mem_row_major);
    __syncthreads();

    const int valid = min(TM, NROWS - row0);

    // BN partials (pad rows are exact zeros)
    {
        int col = t & 127, part = t >> 7;
        float s = 0.f, s2 = 0.f;
        const float* p = stage + col;
#pragma unroll 8
        for (int r = part * 64; r < part * 64 + 64; r++) {
            float v = p[r * CCH];
            s += v; s2 += v * v;
        }
        Pred[part * 256 + col]       = s;
        Pred[part * 256 + 128 + col] = s2;
    }
    // fp16 store of the tile (4 halves per thread-iter, coalesced)
    {
        __half* gp = g_out + ((size_t)a * NROWS + row0) * CCH;
#pragma unroll
        for (int it = 0; it < 16; it++) {
            int vid = t + it * 256;            // 0..4095
            int r   = vid >> 5;
            int u   = vid & 31;
            if (r < valid) {
                const float* sp = stage + r * CCH + u * 4;
                __half2 h0 = __floats2half2_rn(sp[0], sp[1]);
                __half2 h1 = __floats2half2_rn(sp[2], sp[3]);
                *(uint2*)(gp + (size_t)r * CCH + u * 4) =
                    make_uint2(*(uint32_t*)&h0, *(uint32_t*)&h1);
            }
        }
    }
    __syncthreads();
    if (t < CCH) {
        g_part[(((size_t)a * NBLK1 + blockIdx.x) * 2 + 0) * CCH + t] = Pred[t] + Pred[256 + t];
        g_part[(((size_t)a * NBLK1 + blockIdx.x) * 2 + 1) * CCH + t] = Pred[128 + t] + Pred[384 + t];
    }
}

// ---------------------------------------------------------------------------
// K2a/K2b: deterministic two-stage BN reduction; fold BN into scale/offset
// ---------------------------------------------------------------------------
__global__ __launch_bounds__(256) void k2a()
{
    const int a = blockIdx.x, g = blockIdx.y, t = threadIdx.x;
    const int s = t >> 7, c = t & 127;
    const int b1 = min((g + 1) * 64, NBLK1);
    float acc = 0.f;
    for (int b = g * 64; b < b1; b++)
        acc += g_part[(((size_t)a * NBLK1 + b) * 2 + s) * CCH + c];
    g_p2[((a * NCH2 + g) * 2 + s) * CCH + c] = acc;
}
__global__ __launch_bounds__(128) void k2b(const float* __restrict__ gamma,
                                           const float* __restrict__ beta)
{
    const int a = blockIdx.x, t = threadIdx.x;   // t = channel
    double s = 0.0, s2 = 0.0;
    for (int g = 0; g < NCH2; g++) {
        s  += (double)g_p2[((a * NCH2 + g) * 2 + 0) * CCH + t];
        s2 += (double)g_p2[((a * NCH2 + g) * 2 + 1) * CCH + t];
    }
    double mu  = s / (double)NROWS;
    double var = s2 / (double)NROWS - mu * mu;
    float rstd = rsqrtf((float)var + BN_EPS);
    float sc   = rstd * gamma[a * CCH + t];
    g_scale[a * CCH + t] = sc;
    g_off  [a * CCH + t] = beta[a * CCH + t] - (float)mu * sc;
}

// ---------------------------------------------------------------------------
// K3: out = feat * sum_a sigmoid(o_a * sc[a] + off[a])
// ---------------------------------------------------------------------------
__global__ __launch_bounds__(256) void k3_final(const float* __restrict__ feat,
                                                float* __restrict__ out)
{
    const size_t i  = (size_t)blockIdx.x * 256 + threadIdx.x;  // float4 index
    const int cbase = (int)(i & 31) * 4;

    float4 f4 = ((const float4*)feat)[i];
    float acc[4] = { 0.f, 0.f, 0.f, 0.f };

#pragma unroll
    for (int a = 0; a < 3; a++) {
        uint2 h = *(const uint2*)(g_out + (size_t)a * NROWS * CCH + i * 4);
        __half2 h01 = *(__half2*)&h.x;
        __half2 h23 = *(__half2*)&h.y;
        float o[4] = { __low2float(h01), __high2float(h01),
                       __low2float(h23), __high2float(h23) };
#pragma unroll
        for (int j = 0; j < 4; j++) {
            int c = cbase + j;
            float x = fmaf(o[j], g_scale[a * CCH + c], g_off[a * CCH + c]);
            acc[j] += 1.0f / (1.0f + __expf(-x));
        }
    }
    ((float4*)out)[i] = make_float4(acc[0] * f4.x, acc[1] * f4.y,
                                    acc[2] * f4.z, acc[3] * f4.w);
}

// ---------------------------------------------------------------------------
extern "C" void kernel_launch(void* const* d_in, const int* in_sizes, int n_in,
                              void* d_out, int out_size)
{
    const float* feat  = (const float*)d_in[0];
    const int*   nb    = (const int*)  d_in[1];
    const float* W     = (const float*)d_in[2];
    const float* gamma = (const float*)d_in[3];
    const float* beta  = (const float*)d_in[4];

    cudaFuncSetAttribute(k1_gemm, cudaFuncAttributeMaxDynamicSharedMemorySize, DYN_SMEM);

    k0_feat<<<25000, 256>>>(feat);               // 200000*128/4/256
    k0_w<<<144, 256>>>(W);                       // 9*128*128/4/256
    dim3 g1(NBLK1, 3);
    k1_gemm<<<g1, 256, DYN_SMEM>>>(nb);
    dim3 g2(3, NCH2);
    k2a<<<g2, 256>>>();
    k2b<<<3, 128>>>(gamma, beta);
    k3_final<<<25000, 256>>>(feat, (float*)d_out);
}